// round 16
// baseline (speedup 1.0000x reference)
#include <cuda_runtime.h>
#include <cuda_fp16.h>
#include <math.h>

#define INPUT 40
#define HID   512
#define LAT   128
#define BATCH 1024
#define SEQ   512
#define NTH   512
#define CLS   4
#define ROWS  32
#define NBLK  128

#define NKC_H  35   // 48(pad x) + 512
#define NKC_S  40   // 512 + 128
#define NKC_D1 40   // 128 + 512
#define NKC_D2 35   // 512 + 48(pad h2)

typedef unsigned long long u64;
typedef unsigned int u32;

// ---------------- device scratch: A-fragment fp16 weights (tile-indexed) ----------------
__device__ __align__(16) uint4 g_A_h [128 * NKC_H  * 32];
__device__ __align__(16) uint4 g_A_d1[128 * NKC_D1 * 32];
__device__ __align__(16) uint4 g_A_mu[ 32 * NKC_S  * 32];
__device__ __align__(16) uint4 g_A_lv[ 32 * NKC_S  * 32];
__device__ __align__(16) uint4 g_A_d2[ 10 * NKC_D2 * 32];
__device__ float g_b_h [4*HID];
__device__ float g_b_mu[4*LAT];
__device__ float g_b_lv[4*LAT];
__device__ float g_b_d1[4*HID];
__device__ float g_b_d2[4*INPUT];

// ---------------- prep ----------------
__device__ __forceinline__ float wval(const float* Wih, const float* Whh,
                                      int Kinp, int Kpad, int Krec, int gate, int k)
{
    if (k < Kinp) return Wih[gate * Kinp + k];
    if (k >= Kpad && k < Kpad + Krec) return Whh[gate * Krec + (k - Kpad)];
    return 0.f;
}

__device__ __forceinline__ void fill_f16(const float* Wih, const float* Whh,
                                         int Kinp, int Kpad, int Krec, int NT, int NKC,
                                         u32* out, int tid, int nt)
{
    int n = NT * NKC * 128;
    for (int i = tid; i < n; i += nt) {
        int gt  = i / (NKC * 128);
        int rem = i - gt * (NKC * 128);
        int kc  = rem >> 7;
        int l   = rem & 127;
        int lane = l >> 2, reg = l & 3;
        int gate = gt * 16 + (lane >> 2) + ((reg & 1) ? 8 : 0);
        int k    = kc * 16 + (lane & 3) * 2 + ((reg & 2) ? 8 : 0);
        float v0 = wval(Wih, Whh, Kinp, Kpad, Krec, gate, k);
        float v1 = wval(Wih, Whh, Kinp, Kpad, Krec, gate, k + 1);
        __half2 hh = __floats2half2_rn(v0, v1);
        out[i] = *reinterpret_cast<u32*>(&hh);
    }
}

__global__ void prep_kernel(
    const float* Wih_h,  const float* Whh_h,  const float* bih_h,  const float* bhh_h,
    const float* Wih_mu, const float* Whh_mu, const float* bih_mu, const float* bhh_mu,
    const float* Wih_lv, const float* Whh_lv, const float* bih_lv, const float* bhh_lv,
    const float* Wih_d1, const float* Whh_d1, const float* bih_d1, const float* bhh_d1,
    const float* Wih_d2, const float* Whh_d2, const float* bih_d2, const float* bhh_d2)
{
    int tid = blockIdx.x * blockDim.x + threadIdx.x;
    int nt  = gridDim.x * blockDim.x;
    fill_f16(Wih_h,  Whh_h,  INPUT, 48,  HID,   128, NKC_H,  (u32*)g_A_h,  tid, nt);
    fill_f16(Wih_d1, Whh_d1, LAT,   LAT, HID,   128, NKC_D1, (u32*)g_A_d1, tid, nt);
    fill_f16(Wih_mu, Whh_mu, HID,   HID, LAT,    32, NKC_S,  (u32*)g_A_mu, tid, nt);
    fill_f16(Wih_lv, Whh_lv, HID,   HID, LAT,    32, NKC_S,  (u32*)g_A_lv, tid, nt);
    fill_f16(Wih_d2, Whh_d2, HID,   HID, INPUT,  10, NKC_D2, (u32*)g_A_d2, tid, nt);
    for (int i = tid; i < 4*HID;   i += nt) g_b_h[i]  = bih_h[i]  + bhh_h[i];
    for (int i = tid; i < 4*LAT;   i += nt) g_b_mu[i] = bih_mu[i] + bhh_mu[i];
    for (int i = tid; i < 4*LAT;   i += nt) g_b_lv[i] = bih_lv[i] + bhh_lv[i];
    for (int i = tid; i < 4*HID;   i += nt) g_b_d1[i] = bih_d1[i] + bhh_d1[i];
    for (int i = tid; i < 4*INPUT; i += nt) g_b_d2[i] = bih_d2[i] + bhh_d2[i];
}

// ---------------- helpers ----------------
__device__ __forceinline__ float tanh_fast(float x)
{ float y; asm("tanh.approx.f32 %0, %1;" : "=f"(y) : "f"(x)); return y; }
__device__ __forceinline__ float sigf(float x)
{ return fmaf(tanh_fast(0.5f * x), 0.5f, 0.5f); }
__device__ __forceinline__ u32 h2pack(float a, float b)
{ __half2 h = __floats2half2_rn(a, b); return *reinterpret_cast<u32*>(&h); }
__device__ __forceinline__ void cluster_sync_()
{ asm volatile("barrier.cluster.arrive.aligned;\n\tbarrier.cluster.wait.aligned;" ::: "memory"); }
__device__ __forceinline__ unsigned cluster_rank_()
{ unsigned r; asm("mov.u32 %0, %%cluster_ctarank;" : "=r"(r)); return r; }
__device__ __forceinline__ unsigned smem_u32a(const void* p)
{ unsigned a; asm("{ .reg .u64 t; cvta.to.shared.u64 t, %1; cvt.u32.u64 %0, t; }" : "=r"(a) : "l"(p)); return a; }
__device__ __forceinline__ void st_peer_u64(unsigned addr, unsigned peer, u64 v)
{
    asm volatile("{ .reg .b32 ra; mapa.shared::cluster.u32 ra, %0, %1; "
                 "st.shared::cluster.b64 [ra], %2; }" :: "r"(addr), "r"(peer), "l"(v) : "memory");
}
__device__ __forceinline__ void mma16(float (&d)[4], const uint4& a, u32 b0, u32 b1)
{
    asm volatile("mma.sync.aligned.m16n8k16.row.col.f32.f16.f16.f32 "
                 "{%0,%1,%2,%3},{%4,%5,%6,%7},{%8,%9},{%0,%1,%2,%3};"
                 : "+f"(d[0]), "+f"(d[1]), "+f"(d[2]), "+f"(d[3])
                 : "r"(a.x), "r"(a.y), "r"(a.z), "r"(a.w), "r"(b0), "r"(b1));
}

// ---------------- big-cell mma: 2 tiles/warp x 4 n-tiles (32 rows) ----------------
template<int NKC, int XKC>
__device__ __forceinline__ void big_mma4(const uint4* __restrict__ A,
                                         const u32* __restrict__ xz, const u32* __restrict__ hT2,
                                         float* __restrict__ gB, int rank, int w, int lane)
{
    const int tg = lane & 3, gp = lane >> 2;
    const int c = w >> 2, m2b = (w & 3) * 2;
    float acc[2][4][4];
    #pragma unroll
    for (int i = 0; i < 2; i++)
        #pragma unroll
        for (int n = 0; n < 4; n++)
            #pragma unroll
            for (int q = 0; q < 4; q++) acc[i][n][q] = 0.f;

    for (int kc = 0; kc < NKC; kc++) {
        const u32* src; int k2;
        if (kc < XKC) { src = xz;  k2 = kc * 8 + tg; }
        else          { src = hT2; k2 = (kc - XKC) * 8 + tg; }
        u32 b0[4], b1[4];
        #pragma unroll
        for (int n = 0; n < 4; n++) {
            b0[n] = src[k2 * 32 + n * 8 + gp];
            b1[n] = src[(k2 + 4) * 32 + n * 8 + gp];
        }
        #pragma unroll
        for (int i = 0; i < 2; i++) {
            int gt = c * 32 + rank * 8 + m2b + i;
            uint4 a = A[((size_t)gt * NKC + kc) * 32 + lane];
            #pragma unroll
            for (int n = 0; n < 4; n++) mma16(acc[i][n], a, b0[n], b1[n]);
        }
    }
    #pragma unroll
    for (int i = 0; i < 2; i++) {
        int lg = c * 128 + (m2b + i) * 16 + gp;
        #pragma unroll
        for (int n = 0; n < 4; n++) {
            *(float2*)&gB[lg * 32 + n * 8 + 2 * tg]       = make_float2(acc[i][n][0], acc[i][n][1]);
            *(float2*)&gB[(lg + 8) * 32 + n * 8 + 2 * tg] = make_float2(acc[i][n][2], acc[i][n][3]);
        }
    }
}

// ---------------- big-cell elementwise: unit uB (0..127), rows rg*8.. ----------------
__device__ __forceinline__ void big_elem4(const float* __restrict__ gB, const float (&b4)[4],
                                          float (&cR)[8], int uB, int rg, u32 (&hp)[8])
{
    float G[4][8];
    #pragma unroll
    for (int g = 0; g < 4; g++) {
        const float* p = &gB[(g * 128 + uB) * 32 + rg * 8];
        float4 v0 = *(const float4*)p, v1 = *(const float4*)(p + 4);
        G[g][0]=v0.x; G[g][1]=v0.y; G[g][2]=v0.z; G[g][3]=v0.w;
        G[g][4]=v1.x; G[g][5]=v1.y; G[g][6]=v1.z; G[g][7]=v1.w;
    }
    #pragma unroll
    for (int r = 0; r < 8; r++) {
        float cv = sigf(G[1][r] + b4[1]) * cR[r] + sigf(G[0][r] + b4[0]) * tanh_fast(G[2][r] + b4[2]);
        float h  = sigf(G[3][r] + b4[3]) * tanh_fast(cv);
        cR[r] = cv;
        float other = __shfl_xor_sync(0xffffffffu, h, 4);   // partner unit uB^1 (thread t^4)
        hp[r] = h2pack(h, other);                           // valid on even-uB threads
    }
}

// ---------------- main persistent cluster kernel ----------------
extern __shared__ float smem[];

__global__ void __launch_bounds__(NTH, 1) vae_kernel(
    const float* __restrict__ x, const float* __restrict__ eps, float* __restrict__ out)
{
    float* gatesBig = smem;                        // 512 gates x 32 rows = 16384
    float* gatesSml = gatesBig + 16384;            // 256 gates x 32 rows =  8192
    float* d2g      = gatesSml + 8192;             // 160 gates x 8 rows  =  1280
    u32*  hT2  = (u32*)(d2g + 1280);               // [256 k2][32]        =  8192
    u32*  hs2  = hT2 + 8192;                       // [64 k2][32]         =  2048
    u32*  h2T2 = hs2 + 2048;                       // [24 k2][8]          =   192
    u32*  xzA  = h2T2 + 192;                       // [64 k2][32]         =  2048
    u32*  xzB  = xzA + 2048;                       //                        2048
    float* csml = (float*)(xzB + 2048);            // [64 u][32]          =  2048
    float* c2T  = csml + 2048;                     // [40][8]             =   320

    const int t = threadIdx.x, w = t >> 5, lane = t & 31;
    const unsigned rank = cluster_rank_();
    const int sub = (int)rank >> 1;                // small-cell unit-half
    const int r0c = (blockIdx.x >> 2) * ROWS;

    float* reconO = out;
    float* muO    = out + (size_t)BATCH * SEQ * INPUT;
    float* lvO    = muO + (size_t)BATCH * SEQ * LAT;
    const unsigned hT2addr = smem_u32a(hT2);
    const unsigned hs2addr = smem_u32a(hs2);

    // mappings
    const int uB = t >> 2, rgB = t & 3, jB = (int)rank * 128 + uB;   // big elementwise
    const int uS = t >> 3, rqS = t & 7, jS = sub * 64 + uS;          // small elementwise
    // bias preloads
    float bh[4], bd1[4], bs[4], bd2[4];
    #pragma unroll
    for (int c = 0; c < 4; c++) { bh[c] = g_b_h[c*HID + jB]; bd1[c] = g_b_d1[c*HID + jB]; }
    const float* bsp = (rank & 1) ? g_b_lv : g_b_mu;
    #pragma unroll
    for (int c = 0; c < 4; c++) bs[c] = bsp[c*LAT + jS];
    #pragma unroll
    for (int c = 0; c < 4; c++) bd2[c] = (t < 320) ? g_b_d2[c*INPUT + (t >> 3)] : 0.f;

    float cReg[8];

    // ---- encoder init ----
    #pragma unroll
    for (int r = 0; r < 8; r++) cReg[r] = 0.f;
    for (int i = t; i < 8192; i += NTH) hT2[i] = 0u;
    for (int i = t; i < 2048; i += NTH) hs2[i] = 0u;
    for (int i = t; i < 2048; i += NTH) csml[i] = 0.f;
    for (int idx = t; idx < 24 * 32; idx += NTH) {      // stage x_0 (zero-padded to k=48)
        int k2 = idx >> 5, row = idx & 31, k = 2 * k2;
        float v0 = (k < INPUT)     ? x[((size_t)(r0c + row) * SEQ) * INPUT + k]     : 0.f;
        float v1 = (k + 1 < INPUT) ? x[((size_t)(r0c + row) * SEQ) * INPUT + k + 1] : 0.f;
        xzA[idx] = h2pack(v0, v1);
    }
    __syncthreads();

    // ================= encoder =================
    for (int s = 0; s < SEQ; s++) {
        u32* xzC = (s & 1) ? xzB : xzA;
        u32* xzN = (s & 1) ? xzA : xzB;

        big_mma4<NKC_H, 3>(g_A_h, xzC, hT2, gatesBig, (int)rank, w, lane);
        __syncthreads();

        u32 hp[8];
        big_elem4(gatesBig, bh, cReg, uB, rgB, hp);
        cluster_sync_();                    // all CTAs done reading hT2 old

        // publish h (local + 3 peers), stage x_{s+1}
        if ((uB & 1) == 0) {
            int base = (jB >> 1) * 32 + rgB * 8;
            #pragma unroll
            for (int r = 0; r < 8; r++) hT2[base + r] = hp[r];
            #pragma unroll
            for (int pr = 1; pr < 4; pr++) {
                unsigned peer = rank ^ (unsigned)pr;
                #pragma unroll
                for (int r = 0; r < 8; r += 2)
                    st_peer_u64(hT2addr + (unsigned)(base + r) * 4u, peer,
                                (u64)hp[r] | ((u64)hp[r+1] << 32));
            }
        }
        if (s + 1 < SEQ) {
            for (int idx = t; idx < 24 * 32; idx += NTH) {
                int k2 = idx >> 5, row = idx & 31, k = 2 * k2;
                float v0 = (k < INPUT)     ? x[((size_t)(r0c + row) * SEQ + s + 1) * INPUT + k]     : 0.f;
                float v1 = (k + 1 < INPUT) ? x[((size_t)(r0c + row) * SEQ + s + 1) * INPUT + k + 1] : 0.f;
                xzN[idx] = h2pack(v0, v1);
            }
        }
        cluster_sync_();                    // hT2 new visible cluster-wide

        // small mma: mu (CTA0,2) / lv (CTA1,3), unit-half split, 1 tile/warp x 4 n-tiles
        {
            const uint4* A = (rank & 1) ? g_A_lv : g_A_mu;
            const int tg = lane & 3, gp = lane >> 2;
            const int c = w >> 2, m2 = w & 3;
            const int tile = c * 8 + sub * 4 + m2;
            float acc[4][4];
            #pragma unroll
            for (int n = 0; n < 4; n++)
                #pragma unroll
                for (int q = 0; q < 4; q++) acc[n][q] = 0.f;
            for (int kc = 0; kc < NKC_S; kc++) {
                const u32* src; int k2;
                if (kc < 32) { src = hT2; k2 = kc * 8 + tg; }
                else         { src = hs2; k2 = (kc - 32) * 8 + tg; }
                u32 b0[4], b1[4];
                #pragma unroll
                for (int n = 0; n < 4; n++) {
                    b0[n] = src[k2 * 32 + n * 8 + gp];
                    b1[n] = src[(k2 + 4) * 32 + n * 8 + gp];
                }
                uint4 a = A[((size_t)tile * NKC_S + kc) * 32 + lane];
                #pragma unroll
                for (int n = 0; n < 4; n++) mma16(acc[n], a, b0[n], b1[n]);
            }
            int lg = c * 64 + m2 * 16 + gp;
            #pragma unroll
            for (int n = 0; n < 4; n++) {
                *(float2*)&gatesSml[lg * 32 + n * 8 + 2 * tg]       = make_float2(acc[n][0], acc[n][1]);
                *(float2*)&gatesSml[(lg + 8) * 32 + n * 8 + 2 * tg] = make_float2(acc[n][2], acc[n][3]);
            }
        }
        cluster_sync_();   // orders peer hs2 writes below vs all CTAs' hs2 reads above

        // small elementwise: 64 units x 32 rows, 4 rows/thread
        {
            float* outPtr = (rank & 1) ? lvO : muO;
            float G[4][4];
            #pragma unroll
            for (int g = 0; g < 4; g++) {
                float4 v = *(const float4*)&gatesSml[(g * 64 + uS) * 32 + rqS * 4];
                G[g][0]=v.x; G[g][1]=v.y; G[g][2]=v.z; G[g][3]=v.w;
            }
            u32 hq[4];
            #pragma unroll
            for (int rr = 0; rr < 4; rr++) {
                int row = rqS * 4 + rr;
                int ci = uS * 32 + row;
                float cv = sigf(G[1][rr] + bs[1]) * csml[ci] + sigf(G[0][rr] + bs[0]) * tanh_fast(G[2][rr] + bs[2]);
                float h  = sigf(G[3][rr] + bs[3]) * tanh_fast(cv);
                csml[ci] = cv;
                float other = __shfl_xor_sync(0xffffffffu, h, 8);   // partner unit uS^1
                hq[rr] = h2pack(h, other);
                outPtr[((size_t)(r0c + row) * SEQ + s) * LAT + jS] = h;
            }
            if ((uS & 1) == 0) {
                int base = (jS >> 1) * 32 + rqS * 4;
                #pragma unroll
                for (int rr = 0; rr < 4; rr++) hs2[base + rr] = hq[rr];
                unsigned peer = rank ^ 2u;      // other CTA of same cell
                st_peer_u64(hs2addr + (unsigned)base * 4u,       peer, (u64)hq[0] | ((u64)hq[1] << 32));
                st_peer_u64(hs2addr + (unsigned)(base + 2) * 4u, peer, (u64)hq[2] | ((u64)hq[3] << 32));
            }
        }
    }

    // ---- transition ----
    cluster_sync_();
    #pragma unroll
    for (int r = 0; r < 8; r++) cReg[r] = 0.f;
    for (int i = t; i < 8192; i += NTH) hT2[i] = 0u;
    for (int i = t; i < 192;  i += NTH) h2T2[i] = 0u;
    for (int i = t; i < 320;  i += NTH) c2T[i] = 0.f;
    for (int idx = t; idx < 64 * 32; idx += NTH) {      // stage z_0
        int k2 = idx >> 5, row = idx & 31;
        size_t off = ((size_t)(r0c + row) * SEQ) * LAT + 2 * k2;
        float z0 = fmaf(eps[off],     __expf(0.5f * __ldcg(&lvO[off])),     __ldcg(&muO[off]));
        float z1 = fmaf(eps[off + 1], __expf(0.5f * __ldcg(&lvO[off + 1])), __ldcg(&muO[off + 1]));
        xzA[idx] = h2pack(z0, z1);
    }
    __syncthreads();

    // ================= decoder =================
    for (int s = 0; s < SEQ; s++) {
        u32* xzC = (s & 1) ? xzB : xzA;
        u32* xzN = (s & 1) ? xzA : xzB;

        big_mma4<NKC_D1, 8>(g_A_d1, xzC, hT2, gatesBig, (int)rank, w, lane);
        __syncthreads();

        u32 hp[8];
        big_elem4(gatesBig, bd1, cReg, uB, rgB, hp);
        cluster_sync_();

        if ((uB & 1) == 0) {
            int base = (jB >> 1) * 32 + rgB * 8;
            #pragma unroll
            for (int r = 0; r < 8; r++) hT2[base + r] = hp[r];
            #pragma unroll
            for (int pr = 1; pr < 4; pr++) {
                unsigned peer = rank ^ (unsigned)pr;
                #pragma unroll
                for (int r = 0; r < 8; r += 2)
                    st_peer_u64(hT2addr + (unsigned)(base + r) * 4u, peer,
                                (u64)hp[r] | ((u64)hp[r+1] << 32));
            }
        }
        if (s + 1 < SEQ) {
            for (int idx = t; idx < 64 * 32; idx += NTH) {
                int k2 = idx >> 5, row = idx & 31;
                size_t off = ((size_t)(r0c + row) * SEQ + s + 1) * LAT + 2 * k2;
                float z0 = fmaf(eps[off],     __expf(0.5f * __ldcg(&lvO[off])),     __ldcg(&muO[off]));
                float z1 = fmaf(eps[off + 1], __expf(0.5f * __ldcg(&lvO[off + 1])), __ldcg(&muO[off + 1]));
                xzN[idx] = h2pack(z0, z1);
            }
        }
        cluster_sync_();

        // d2 mma: warps 0..9, 1 tile each, this CTA's local 8 rows (rank*8..)
        if (w < 10) {
            const int tg = lane & 3, gp = lane >> 2;
            float acc[4] = {0.f, 0.f, 0.f, 0.f};
            for (int kc = 0; kc < NKC_D2; kc++) {
                u32 b0, b1;
                if (kc < 32) {
                    int k2 = kc * 8 + tg;
                    b0 = hT2[k2 * 32 + (int)rank * 8 + gp];
                    b1 = hT2[(k2 + 4) * 32 + (int)rank * 8 + gp];
                } else {
                    int k2 = (kc - 32) * 8 + tg;
                    b0 = h2T2[k2 * 8 + gp];
                    b1 = h2T2[(k2 + 4) * 8 + gp];
                }
                uint4 a = g_A_d2[((size_t)w * NKC_D2 + kc) * 32 + lane];
                mma16(acc, a, b0, b1);
            }
            *(float2*)&d2g[(w * 16 + gp) * 8 + 2 * tg]     = make_float2(acc[0], acc[1]);
            *(float2*)&d2g[(w * 16 + gp + 8) * 8 + 2 * tg] = make_float2(acc[2], acc[3]);
        }
        __syncthreads();

        // d2 elementwise: 320 unit-rows (local 8 rows)
        if (t < 320) {
            int u2 = t >> 3, row = t & 7;
            float G[4];
            #pragma unroll
            for (int g = 0; g < 4; g++) G[g] = d2g[(g * 40 + u2) * 8 + row];
            int ci = u2 * 8 + row;
            float cv = sigf(G[1] + bd2[1]) * c2T[ci] + sigf(G[0] + bd2[0]) * tanh_fast(G[2] + bd2[2]);
            float h  = sigf(G[3] + bd2[3]) * tanh_fast(cv);
            c2T[ci] = cv;
            float other = __shfl_xor_sync(0xffffffffu, h, 8);
            if ((u2 & 1) == 0) h2T2[(u2 >> 1) * 8 + row] = h2pack(h, other);
            reconO[((size_t)(r0c + (int)rank * 8 + row) * SEQ + s) * INPUT + u2] = h;
        }
    }
}

// ---------------- launcher ----------------
extern "C" void kernel_launch(void* const* d_in, const int* in_sizes, int n_in,
                              void* d_out, int out_size)
{
    (void)in_sizes; (void)n_in; (void)out_size;
    const float* x   = (const float*)d_in[0];
    const float* eps = (const float*)d_in[1];

    prep_kernel<<<512, 256>>>(
        (const float*)d_in[2],  (const float*)d_in[3],  (const float*)d_in[4],  (const float*)d_in[5],
        (const float*)d_in[6],  (const float*)d_in[7],  (const float*)d_in[8],  (const float*)d_in[9],
        (const float*)d_in[10], (const float*)d_in[11], (const float*)d_in[12], (const float*)d_in[13],
        (const float*)d_in[14], (const float*)d_in[15], (const float*)d_in[16], (const float*)d_in[17],
        (const float*)d_in[18], (const float*)d_in[19], (const float*)d_in[20], (const float*)d_in[21]);

    const int SMEM_BYTES = (16384 + 8192 + 1280 + 8192 + 2048 + 192 + 2048 + 2048 + 2048 + 320) * 4;
    cudaFuncSetAttribute(vae_kernel, cudaFuncAttributeMaxDynamicSharedMemorySize, SMEM_BYTES);
    cudaFuncSetAttribute(vae_kernel, cudaFuncAttributeNonPortableClusterSizeAllowed, 1);

    cudaLaunchConfig_t cfg = {};
    cfg.gridDim  = dim3(NBLK, 1, 1);
    cfg.blockDim = dim3(NTH, 1, 1);
    cfg.dynamicSmemBytes = SMEM_BYTES;
    cudaLaunchAttribute attrs[1];
    attrs[0].id = cudaLaunchAttributeClusterDimension;
    attrs[0].val.clusterDim.x = CLS;
    attrs[0].val.clusterDim.y = 1;
    attrs[0].val.clusterDim.z = 1;
    cfg.attrs = attrs;
    cfg.numAttrs = 1;
    cudaLaunchKernelEx(&cfg, vae_kernel, x, eps, (float*)d_out);
}

// round 17
// speedup vs baseline: 1.0064x; 1.0064x over previous
#include <cuda_runtime.h>
#include <cuda_fp16.h>
#include <math.h>

#define INPUT 40
#define HID   512
#define LAT   128
#define BATCH 1024
#define SEQ   512
#define NTH   512
#define CLS   4
#define ROWS  32
#define NBLK  128
#define STR   34    // padded row stride (in 4B units) for 32-row arrays: conflict-free

#define NKC_H  35   // 48(pad x) + 512
#define NKC_S  40   // 512 + 128
#define NKC_D1 40   // 128 + 512
#define NKC_D2 35   // 512 + 48(pad h2)

typedef unsigned long long u64;
typedef unsigned int u32;

// ---------------- device scratch: A-fragment fp16 weights (tile-indexed) ----------------
__device__ __align__(16) uint4 g_A_h [128 * NKC_H  * 32];
__device__ __align__(16) uint4 g_A_d1[128 * NKC_D1 * 32];
__device__ __align__(16) uint4 g_A_mu[ 32 * NKC_S  * 32];
__device__ __align__(16) uint4 g_A_lv[ 32 * NKC_S  * 32];
__device__ __align__(16) uint4 g_A_d2[ 10 * NKC_D2 * 32];
__device__ float g_b_h [4*HID];
__device__ float g_b_mu[4*LAT];
__device__ float g_b_lv[4*LAT];
__device__ float g_b_d1[4*HID];
__device__ float g_b_d2[4*INPUT];

// ---------------- prep ----------------
__device__ __forceinline__ float wval(const float* Wih, const float* Whh,
                                      int Kinp, int Kpad, int Krec, int gate, int k)
{
    if (k < Kinp) return Wih[gate * Kinp + k];
    if (k >= Kpad && k < Kpad + Krec) return Whh[gate * Krec + (k - Kpad)];
    return 0.f;
}

__device__ __forceinline__ void fill_f16(const float* Wih, const float* Whh,
                                         int Kinp, int Kpad, int Krec, int NT, int NKC,
                                         u32* out, int tid, int nt)
{
    int n = NT * NKC * 128;
    for (int i = tid; i < n; i += nt) {
        int gt  = i / (NKC * 128);
        int rem = i - gt * (NKC * 128);
        int kc  = rem >> 7;
        int l   = rem & 127;
        int lane = l >> 2, reg = l & 3;
        int gate = gt * 16 + (lane >> 2) + ((reg & 1) ? 8 : 0);
        int k    = kc * 16 + (lane & 3) * 2 + ((reg & 2) ? 8 : 0);
        float v0 = wval(Wih, Whh, Kinp, Kpad, Krec, gate, k);
        float v1 = wval(Wih, Whh, Kinp, Kpad, Krec, gate, k + 1);
        __half2 hh = __floats2half2_rn(v0, v1);
        out[i] = *reinterpret_cast<u32*>(&hh);
    }
}

__global__ void prep_kernel(
    const float* Wih_h,  const float* Whh_h,  const float* bih_h,  const float* bhh_h,
    const float* Wih_mu, const float* Whh_mu, const float* bih_mu, const float* bhh_mu,
    const float* Wih_lv, const float* Whh_lv, const float* bih_lv, const float* bhh_lv,
    const float* Wih_d1, const float* Whh_d1, const float* bih_d1, const float* bhh_d1,
    const float* Wih_d2, const float* Whh_d2, const float* bih_d2, const float* bhh_d2)
{
    int tid = blockIdx.x * blockDim.x + threadIdx.x;
    int nt  = gridDim.x * blockDim.x;
    fill_f16(Wih_h,  Whh_h,  INPUT, 48,  HID,   128, NKC_H,  (u32*)g_A_h,  tid, nt);
    fill_f16(Wih_d1, Whh_d1, LAT,   LAT, HID,   128, NKC_D1, (u32*)g_A_d1, tid, nt);
    fill_f16(Wih_mu, Whh_mu, HID,   HID, LAT,    32, NKC_S,  (u32*)g_A_mu, tid, nt);
    fill_f16(Wih_lv, Whh_lv, HID,   HID, LAT,    32, NKC_S,  (u32*)g_A_lv, tid, nt);
    fill_f16(Wih_d2, Whh_d2, HID,   HID, INPUT,  10, NKC_D2, (u32*)g_A_d2, tid, nt);
    for (int i = tid; i < 4*HID;   i += nt) g_b_h[i]  = bih_h[i]  + bhh_h[i];
    for (int i = tid; i < 4*LAT;   i += nt) g_b_mu[i] = bih_mu[i] + bhh_mu[i];
    for (int i = tid; i < 4*LAT;   i += nt) g_b_lv[i] = bih_lv[i] + bhh_lv[i];
    for (int i = tid; i < 4*HID;   i += nt) g_b_d1[i] = bih_d1[i] + bhh_d1[i];
    for (int i = tid; i < 4*INPUT; i += nt) g_b_d2[i] = bih_d2[i] + bhh_d2[i];
}

// ---------------- helpers ----------------
__device__ __forceinline__ float tanh_fast(float x)
{ float y; asm("tanh.approx.f32 %0, %1;" : "=f"(y) : "f"(x)); return y; }
__device__ __forceinline__ float sigf(float x)
{ return fmaf(tanh_fast(0.5f * x), 0.5f, 0.5f); }
__device__ __forceinline__ u32 h2pack(float a, float b)
{ __half2 h = __floats2half2_rn(a, b); return *reinterpret_cast<u32*>(&h); }
__device__ __forceinline__ void cluster_sync_()
{ asm volatile("barrier.cluster.arrive.aligned;\n\tbarrier.cluster.wait.aligned;" ::: "memory"); }
__device__ __forceinline__ unsigned cluster_rank_()
{ unsigned r; asm("mov.u32 %0, %%cluster_ctarank;" : "=r"(r)); return r; }
__device__ __forceinline__ unsigned smem_u32a(const void* p)
{ unsigned a; asm("{ .reg .u64 t; cvta.to.shared.u64 t, %1; cvt.u32.u64 %0, t; }" : "=r"(a) : "l"(p)); return a; }
__device__ __forceinline__ void st_peer_u64(unsigned addr, unsigned peer, u64 v)
{
    asm volatile("{ .reg .b32 ra; mapa.shared::cluster.u32 ra, %0, %1; "
                 "st.shared::cluster.b64 [ra], %2; }" :: "r"(addr), "r"(peer), "l"(v) : "memory");
}
__device__ __forceinline__ void mma16(float (&d)[4], const uint4& a, u32 b0, u32 b1)
{
    asm volatile("mma.sync.aligned.m16n8k16.row.col.f32.f16.f16.f32 "
                 "{%0,%1,%2,%3},{%4,%5,%6,%7},{%8,%9},{%0,%1,%2,%3};"
                 : "+f"(d[0]), "+f"(d[1]), "+f"(d[2]), "+f"(d[3])
                 : "r"(a.x), "r"(a.y), "r"(a.z), "r"(a.w), "r"(b0), "r"(b1));
}

// ---------------- big-cell mma: 2 tiles/warp x 4 n-tiles (32 rows) ----------------
template<int NKC, int XKC>
__device__ __forceinline__ void big_mma4(const uint4* __restrict__ A,
                                         const u32* __restrict__ xz, const u32* __restrict__ hT2,
                                         float* __restrict__ gB, int rank, int w, int lane)
{
    const int tg = lane & 3, gp = lane >> 2;
    const int c = w >> 2, m2b = (w & 3) * 2;
    float acc[2][4][4];
    #pragma unroll
    for (int i = 0; i < 2; i++)
        #pragma unroll
        for (int n = 0; n < 4; n++)
            #pragma unroll
            for (int q = 0; q < 4; q++) acc[i][n][q] = 0.f;

    for (int kc = 0; kc < NKC; kc++) {
        const u32* src; int k2;
        if (kc < XKC) { src = xz;  k2 = kc * 8 + tg; }
        else          { src = hT2; k2 = (kc - XKC) * 8 + tg; }
        u32 b0[4], b1[4];
        #pragma unroll
        for (int n = 0; n < 4; n++) {
            b0[n] = src[k2 * STR + n * 8 + gp];
            b1[n] = src[(k2 + 4) * STR + n * 8 + gp];
        }
        #pragma unroll
        for (int i = 0; i < 2; i++) {
            int gt = c * 32 + rank * 8 + m2b + i;
            uint4 a = A[((size_t)gt * NKC + kc) * 32 + lane];
            #pragma unroll
            for (int n = 0; n < 4; n++) mma16(acc[i][n], a, b0[n], b1[n]);
        }
    }
    #pragma unroll
    for (int i = 0; i < 2; i++) {
        int lg = c * 128 + (m2b + i) * 16 + gp;
        #pragma unroll
        for (int n = 0; n < 4; n++) {
            *(float2*)&gB[lg * STR + n * 8 + 2 * tg]       = make_float2(acc[i][n][0], acc[i][n][1]);
            *(float2*)&gB[(lg + 8) * STR + n * 8 + 2 * tg] = make_float2(acc[i][n][2], acc[i][n][3]);
        }
    }
}

// ---------------- big-cell elementwise: unit uB (0..127), rows rg*8.. ----------------
__device__ __forceinline__ void big_elem4(const float* __restrict__ gB, const float (&b4)[4],
                                          float (&cR)[8], int uB, int rg, u32 (&hp)[8])
{
    float G[4][8];
    #pragma unroll
    for (int g = 0; g < 4; g++) {
        const float* p = &gB[(g * 128 + uB) * STR + rg * 8];
        #pragma unroll
        for (int q = 0; q < 4; q++) {
            float2 v = *(const float2*)(p + 2 * q);
            G[g][2*q] = v.x; G[g][2*q+1] = v.y;
        }
    }
    #pragma unroll
    for (int r = 0; r < 8; r++) {
        float cv = sigf(G[1][r] + b4[1]) * cR[r] + sigf(G[0][r] + b4[0]) * tanh_fast(G[2][r] + b4[2]);
        float h  = sigf(G[3][r] + b4[3]) * tanh_fast(cv);
        cR[r] = cv;
        float other = __shfl_xor_sync(0xffffffffu, h, 4);   // partner unit uB^1 (thread t^4)
        hp[r] = h2pack(h, other);                           // valid on even-uB threads
    }
}

// ---------------- main persistent cluster kernel ----------------
extern __shared__ float smem[];

__global__ void __launch_bounds__(NTH, 1) vae_kernel(
    const float* __restrict__ x, const float* __restrict__ eps, float* __restrict__ out)
{
    float* gatesBig = smem;                        // 512 x STR = 17408
    float* gatesSml = gatesBig + 512 * STR;        // 256 x STR =  8704
    float* d2g      = gatesSml + 256 * STR;        // 160 x 8   =  1280
    u32*  hT2  = (u32*)(d2g + 1280);               // 256 k2 x STR = 8704
    u32*  hs2  = hT2 + 256 * STR;                  // 64 k2 x STR  = 2176
    u32*  h2T2 = hs2 + 64 * STR;                   // 24 k2 x 8    =  192
    u32*  xzA  = h2T2 + 192;                       // 64 k2 x STR  = 2176
    u32*  xzB  = xzA + 64 * STR;                   //                2176
    float* csml = (float*)(xzB + 64 * STR);        // 64 u x STR   = 2176
    float* c2T  = csml + 64 * STR;                 // 40 x 8       =  320

    const int t = threadIdx.x, w = t >> 5, lane = t & 31;
    const unsigned rank = cluster_rank_();
    const int sub = (int)rank >> 1;
    const int r0c = (blockIdx.x >> 2) * ROWS;

    float* reconO = out;
    float* muO    = out + (size_t)BATCH * SEQ * INPUT;
    float* lvO    = muO + (size_t)BATCH * SEQ * LAT;
    const unsigned hT2addr = smem_u32a(hT2);
    const unsigned hs2addr = smem_u32a(hs2);

    // mappings
    const int uB = t >> 2, rgB = t & 3, jB = (int)rank * 128 + uB;   // big elementwise
    const int uS = t >> 3, rqS = t & 7, jS = sub * 64 + uS;          // small elementwise
    // bias preloads
    float bh[4], bd1[4], bs[4], bd2[4];
    #pragma unroll
    for (int c = 0; c < 4; c++) { bh[c] = g_b_h[c*HID + jB]; bd1[c] = g_b_d1[c*HID + jB]; }
    const float* bsp = (rank & 1) ? g_b_lv : g_b_mu;
    #pragma unroll
    for (int c = 0; c < 4; c++) bs[c] = bsp[c*LAT + jS];
    #pragma unroll
    for (int c = 0; c < 4; c++) bd2[c] = (t < 320) ? g_b_d2[c*INPUT + (t >> 3)] : 0.f;

    float cReg[8];

    // ---- encoder init ----
    #pragma unroll
    for (int r = 0; r < 8; r++) cReg[r] = 0.f;
    for (int i = t; i < 256 * STR; i += NTH) hT2[i] = 0u;
    for (int i = t; i < 64 * STR;  i += NTH) hs2[i] = 0u;
    for (int i = t; i < 64 * STR;  i += NTH) csml[i] = 0.f;
    for (int idx = t; idx < 24 * 32; idx += NTH) {      // stage x_0 (zero-padded to k=48)
        int k2 = idx >> 5, row = idx & 31, k = 2 * k2;
        float v0 = (k < INPUT)     ? x[((size_t)(r0c + row) * SEQ) * INPUT + k]     : 0.f;
        float v1 = (k + 1 < INPUT) ? x[((size_t)(r0c + row) * SEQ) * INPUT + k + 1] : 0.f;
        xzA[k2 * STR + row] = h2pack(v0, v1);
    }
    __syncthreads();

    // ================= encoder =================
    for (int s = 0; s < SEQ; s++) {
        u32* xzC = (s & 1) ? xzB : xzA;
        u32* xzN = (s & 1) ? xzA : xzB;

        big_mma4<NKC_H, 3>(g_A_h, xzC, hT2, gatesBig, (int)rank, w, lane);
        __syncthreads();

        u32 hp[8];
        big_elem4(gatesBig, bh, cReg, uB, rgB, hp);
        cluster_sync_();                    // all CTAs done reading hT2 old

        // publish h (local + 3 peers), stage x_{s+1}
        if ((uB & 1) == 0) {
            int base = (jB >> 1) * STR + rgB * 8;
            #pragma unroll
            for (int r = 0; r < 8; r++) hT2[base + r] = hp[r];
            #pragma unroll
            for (int pr = 1; pr < 4; pr++) {
                unsigned peer = rank ^ (unsigned)pr;
                #pragma unroll
                for (int r = 0; r < 8; r += 2)
                    st_peer_u64(hT2addr + (unsigned)(base + r) * 4u, peer,
                                (u64)hp[r] | ((u64)hp[r+1] << 32));
            }
        }
        if (s + 1 < SEQ) {
            for (int idx = t; idx < 24 * 32; idx += NTH) {
                int k2 = idx >> 5, row = idx & 31, k = 2 * k2;
                float v0 = (k < INPUT)     ? x[((size_t)(r0c + row) * SEQ + s + 1) * INPUT + k]     : 0.f;
                float v1 = (k + 1 < INPUT) ? x[((size_t)(r0c + row) * SEQ + s + 1) * INPUT + k + 1] : 0.f;
                xzN[k2 * STR + row] = h2pack(v0, v1);
            }
        }
        cluster_sync_();                    // hT2 new visible cluster-wide

        // small mma: mu (CTA0,2) / lv (CTA1,3), unit-half split, 1 tile/warp x 4 n-tiles
        {
            const uint4* A = (rank & 1) ? g_A_lv : g_A_mu;
            const int tg = lane & 3, gp = lane >> 2;
            const int c = w >> 2, m2 = w & 3;
            const int tile = c * 8 + sub * 4 + m2;
            float acc[4][4];
            #pragma unroll
            for (int n = 0; n < 4; n++)
                #pragma unroll
                for (int q = 0; q < 4; q++) acc[n][q] = 0.f;
            for (int kc = 0; kc < NKC_S; kc++) {
                const u32* src; int k2;
                if (kc < 32) { src = hT2; k2 = kc * 8 + tg; }
                else         { src = hs2; k2 = (kc - 32) * 8 + tg; }
                u32 b0[4], b1[4];
                #pragma unroll
                for (int n = 0; n < 4; n++) {
                    b0[n] = src[k2 * STR + n * 8 + gp];
                    b1[n] = src[(k2 + 4) * STR + n * 8 + gp];
                }
                uint4 a = A[((size_t)tile * NKC_S + kc) * 32 + lane];
                #pragma unroll
                for (int n = 0; n < 4; n++) mma16(acc[n], a, b0[n], b1[n]);
            }
            int lg = c * 64 + m2 * 16 + gp;
            #pragma unroll
            for (int n = 0; n < 4; n++) {
                *(float2*)&gatesSml[lg * STR + n * 8 + 2 * tg]       = make_float2(acc[n][0], acc[n][1]);
                *(float2*)&gatesSml[(lg + 8) * STR + n * 8 + 2 * tg] = make_float2(acc[n][2], acc[n][3]);
            }
        }
        cluster_sync_();   // orders peer hs2 writes below vs all CTAs' hs2 reads above

        // small elementwise: 64 units x 32 rows, 4 rows/thread
        {
            float* outPtr = (rank & 1) ? lvO : muO;
            float G[4][4];
            #pragma unroll
            for (int g = 0; g < 4; g++) {
                const float* p = &gatesSml[(g * 64 + uS) * STR + rqS * 4];
                float2 v0 = *(const float2*)p, v1 = *(const float2*)(p + 2);
                G[g][0]=v0.x; G[g][1]=v0.y; G[g][2]=v1.x; G[g][3]=v1.y;
            }
            u32 hq[4];
            #pragma unroll
            for (int rr = 0; rr < 4; rr++) {
                int row = rqS * 4 + rr;
                int ci = uS * STR + row;
                float cv = sigf(G[1][rr] + bs[1]) * csml[ci] + sigf(G[0][rr] + bs[0]) * tanh_fast(G[2][rr] + bs[2]);
                float h  = sigf(G[3][rr] + bs[3]) * tanh_fast(cv);
                csml[ci] = cv;
                float other = __shfl_xor_sync(0xffffffffu, h, 8);   // partner unit uS^1
                hq[rr] = h2pack(h, other);
                outPtr[((size_t)(r0c + row) * SEQ + s) * LAT + jS] = h;
            }
            if ((uS & 1) == 0) {
                int base = (jS >> 1) * STR + rqS * 4;
                #pragma unroll
                for (int rr = 0; rr < 4; rr++) hs2[base + rr] = hq[rr];
                unsigned peer = rank ^ 2u;      // other CTA of same cell
                st_peer_u64(hs2addr + (unsigned)base * 4u,       peer, (u64)hq[0] | ((u64)hq[1] << 32));
                st_peer_u64(hs2addr + (unsigned)(base + 2) * 4u, peer, (u64)hq[2] | ((u64)hq[3] << 32));
            }
        }
    }

    // ---- transition ----
    cluster_sync_();
    #pragma unroll
    for (int r = 0; r < 8; r++) cReg[r] = 0.f;
    for (int i = t; i < 256 * STR; i += NTH) hT2[i] = 0u;
    for (int i = t; i < 192;  i += NTH) h2T2[i] = 0u;
    for (int i = t; i < 320;  i += NTH) c2T[i] = 0.f;
    for (int idx = t; idx < 64 * 32; idx += NTH) {      // stage z_0
        int k2 = idx >> 5, row = idx & 31;
        size_t off = ((size_t)(r0c + row) * SEQ) * LAT + 2 * k2;
        float z0 = fmaf(eps[off],     __expf(0.5f * __ldcg(&lvO[off])),     __ldcg(&muO[off]));
        float z1 = fmaf(eps[off + 1], __expf(0.5f * __ldcg(&lvO[off + 1])), __ldcg(&muO[off + 1]));
        xzA[k2 * STR + row] = h2pack(z0, z1);
    }
    __syncthreads();

    // ================= decoder =================
    for (int s = 0; s < SEQ; s++) {
        u32* xzC = (s & 1) ? xzB : xzA;
        u32* xzN = (s & 1) ? xzA : xzB;

        big_mma4<NKC_D1, 8>(g_A_d1, xzC, hT2, gatesBig, (int)rank, w, lane);
        __syncthreads();

        u32 hp[8];
        big_elem4(gatesBig, bd1, cReg, uB, rgB, hp);
        cluster_sync_();

        if ((uB & 1) == 0) {
            int base = (jB >> 1) * STR + rgB * 8;
            #pragma unroll
            for (int r = 0; r < 8; r++) hT2[base + r] = hp[r];
            #pragma unroll
            for (int pr = 1; pr < 4; pr++) {
                unsigned peer = rank ^ (unsigned)pr;
                #pragma unroll
                for (int r = 0; r < 8; r += 2)
                    st_peer_u64(hT2addr + (unsigned)(base + r) * 4u, peer,
                                (u64)hp[r] | ((u64)hp[r+1] << 32));
            }
        }
        if (s + 1 < SEQ) {
            for (int idx = t; idx < 64 * 32; idx += NTH) {
                int k2 = idx >> 5, row = idx & 31;
                size_t off = ((size_t)(r0c + row) * SEQ + s + 1) * LAT + 2 * k2;
                float z0 = fmaf(eps[off],     __expf(0.5f * __ldcg(&lvO[off])),     __ldcg(&muO[off]));
                float z1 = fmaf(eps[off + 1], __expf(0.5f * __ldcg(&lvO[off + 1])), __ldcg(&muO[off + 1]));
                xzN[k2 * STR + row] = h2pack(z0, z1);
            }
        }
        cluster_sync_();

        // d2 mma: warps 0..9, 1 tile each, this CTA's local 8 rows (rank*8..)
        if (w < 10) {
            const int tg = lane & 3, gp = lane >> 2;
            float acc[4] = {0.f, 0.f, 0.f, 0.f};
            for (int kc = 0; kc < NKC_D2; kc++) {
                u32 b0, b1;
                if (kc < 32) {
                    int k2 = kc * 8 + tg;
                    b0 = hT2[k2 * STR + (int)rank * 8 + gp];
                    b1 = hT2[(k2 + 4) * STR + (int)rank * 8 + gp];
                } else {
                    int k2 = (kc - 32) * 8 + tg;
                    b0 = h2T2[k2 * 8 + gp];
                    b1 = h2T2[(k2 + 4) * 8 + gp];
                }
                uint4 a = g_A_d2[((size_t)w * NKC_D2 + kc) * 32 + lane];
                mma16(acc, a, b0, b1);
            }
            *(float2*)&d2g[(w * 16 + gp) * 8 + 2 * tg]     = make_float2(acc[0], acc[1]);
            *(float2*)&d2g[(w * 16 + gp + 8) * 8 + 2 * tg] = make_float2(acc[2], acc[3]);
        }
        __syncthreads();

        // d2 elementwise: 320 unit-rows (local 8 rows)
        if (t < 320) {
            int u2 = t >> 3, row = t & 7;
            float G[4];
            #pragma unroll
            for (int g = 0; g < 4; g++) G[g] = d2g[(g * 40 + u2) * 8 + row];
            int ci = u2 * 8 + row;
            float cv = sigf(G[1] + bd2[1]) * c2T[ci] + sigf(G[0] + bd2[0]) * tanh_fast(G[2] + bd2[2]);
            float h  = sigf(G[3] + bd2[3]) * tanh_fast(cv);
            c2T[ci] = cv;
            float other = __shfl_xor_sync(0xffffffffu, h, 8);
            if ((u2 & 1) == 0) h2T2[(u2 >> 1) * 8 + row] = h2pack(h, other);
            reconO[((size_t)(r0c + (int)rank * 8 + row) * SEQ + s) * INPUT + u2] = h;
        }
    }
}

// ---------------- launcher ----------------
extern "C" void kernel_launch(void* const* d_in, const int* in_sizes, int n_in,
                              void* d_out, int out_size)
{
    (void)in_sizes; (void)n_in; (void)out_size;
    const float* x   = (const float*)d_in[0];
    const float* eps = (const float*)d_in[1];

    prep_kernel<<<512, 256>>>(
        (const float*)d_in[2],  (const float*)d_in[3],  (const float*)d_in[4],  (const float*)d_in[5],
        (const float*)d_in[6],  (const float*)d_in[7],  (const float*)d_in[8],  (const float*)d_in[9],
        (const float*)d_in[10], (const float*)d_in[11], (const float*)d_in[12], (const float*)d_in[13],
        (const float*)d_in[14], (const float*)d_in[15], (const float*)d_in[16], (const float*)d_in[17],
        (const float*)d_in[18], (const float*)d_in[19], (const float*)d_in[20], (const float*)d_in[21]);

    // smem: gatesBig 512*STR + gatesSml 256*STR + d2g 1280 + hT2 256*STR + hs2 64*STR
    //      + h2T2 192 + xzA 64*STR + xzB 64*STR + csml 64*STR + c2T 320   (4B units)
    const int SMEM_BYTES = (512*STR + 256*STR + 1280 + 256*STR + 64*STR
                          + 192 + 64*STR + 64*STR + 64*STR + 320) * 4;
    cudaFuncSetAttribute(vae_kernel, cudaFuncAttributeMaxDynamicSharedMemorySize, SMEM_BYTES);
    cudaFuncSetAttribute(vae_kernel, cudaFuncAttributeNonPortableClusterSizeAllowed, 1);

    cudaLaunchConfig_t cfg = {};
    cfg.gridDim  = dim3(NBLK, 1, 1);
    cfg.blockDim = dim3(NTH, 1, 1);
    cfg.dynamicSmemBytes = SMEM_BYTES;
    cudaLaunchAttribute attrs[1];
    attrs[0].id = cudaLaunchAttributeClusterDimension;
    attrs[0].val.clusterDim.x = CLS;
    attrs[0].val.clusterDim.y = 1;
    attrs[0].val.clusterDim.z = 1;
    cfg.attrs = attrs;
    cfg.numAttrs = 1;
    cudaLaunchKernelEx(&cfg, vae_kernel, x, eps, (float*)d_out);
}